// round 8
// baseline (speedup 1.0000x reference)
#include <cuda_runtime.h>
#include <math.h>

#define NN     4096
#define DD     256
#define E0N    131072
#define EN     (E0N + NN)      // 135168 (with self loops)
#define KK     2048
#define NEG_SLOPE 0.2f

#define XOUT_OFF 0
#define AC_OFF   (KK * DD)                 // 524288
#define PERM_OFF (AC_OFF + KK * KK)        // 4718592

#define PTILE  4
#define ACT    256   // threads in k_ac

// ---------------- device scratch (static, no allocation) ----------------
__device__ int    g_cnt_dst[NN];
__device__ int    g_cnt_src[NN];
__device__ int    g_rp_dst[NN + 1];
__device__ int    g_rp_src[NN + 1];
__device__ int    g_off_dst[NN];
__device__ int    g_off_src[NN];
__device__ int    g_esrc[EN];     // dst-CSR: src node of each in-edge
__device__ float2 g_epack[EN];    // dst-CSR: (src as int bits, normalized score)
__device__ int    g_edst[EN];     // src-CSR: dst node of each out-edge
__device__ float  g_ew[EN];       // src-CSR: edge weight
__device__ float  g_v[DD];        // lin_w @ att_top
__device__ float  g_cconst;       // lin_b . att_top + att_b
__device__ float  g_sscore[NN];   // x[j] . att_bot
__device__ float  g_xn[NN * DD];
__device__ float  g_a[NN];
__device__ float  g_basev[NN];
__device__ float  g_fit[NN];
__device__ int    g_perm[KK];

// ---------------- kernels ----------------
__global__ void k_zero() {
    int i = blockIdx.x * blockDim.x + threadIdx.x;
    if (i < NN) { g_cnt_dst[i] = 0; g_cnt_src[i] = 0; }
}

__global__ void k_count(const int* __restrict__ ei) {
    int e = blockIdx.x * blockDim.x + threadIdx.x;
    if (e < E0N) {
        atomicAdd(&g_cnt_dst[ei[E0N + e]], 1);
        atomicAdd(&g_cnt_src[ei[e]], 1);
    }
}

// grid=2: block 0 scans dst counts, block 1 scans src counts.
// Adds the implicit +1 self loop per node and writes both rp and off.
__global__ void k_scan2() {
    __shared__ int sp[1024];
    const int* cnt = (blockIdx.x == 0) ? g_cnt_dst : g_cnt_src;
    int* rp  = (blockIdx.x == 0) ? g_rp_dst  : g_rp_src;
    int* off = (blockIdx.x == 0) ? g_off_dst : g_off_src;
    int tid = threadIdx.x;
    int base = tid * 4;
    int loc[4];
    int s = 0;
#pragma unroll
    for (int j = 0; j < 4; j++) { loc[j] = cnt[base + j] + 1; s += loc[j]; }
    sp[tid] = s;
    __syncthreads();
    for (int o = 1; o < 1024; o <<= 1) {
        int v = 0;
        if (tid >= o) v = sp[tid - o];
        __syncthreads();
        if (tid >= o) sp[tid] += v;
        __syncthreads();
    }
    int run = (tid > 0) ? sp[tid - 1] : 0;
#pragma unroll
    for (int j = 0; j < 4; j++) { rp[base + j] = run; off[base + j] = run; run += loc[j]; }
    if (tid == 1023) rp[NN] = run;
}

__global__ void k_fill(const int* __restrict__ ei, const float* __restrict__ ew) {
    int t = blockIdx.x * blockDim.x + threadIdx.x;
    if (t >= E0N + NN) return;
    int s, d; float w;
    if (t < E0N) { s = ei[t]; d = ei[E0N + t]; w = ew[t]; }
    else         { s = t - E0N; d = s; w = 1.0f; }
    int slot = atomicAdd(&g_off_dst[d], 1);
    g_esrc[slot] = s;
    int slot2 = atomicAdd(&g_off_src[s], 1);
    g_edst[slot2] = d;
    g_ew[slot2] = w;
}

__device__ __forceinline__ float blk_reduce(float val, float* red) {
    int tid = threadIdx.x;
    red[tid] = val;
    __syncthreads();
    for (int off = 128; off > 0; off >>= 1) {
        if (tid < off) red[tid] += red[tid + off];
        __syncthreads();
    }
    float r = red[0];
    __syncthreads();
    return r;
}

// fused small precomputations: sscore (NN blocks) | v (DD blocks) | c (1 block)
__global__ void k_pre(const float* __restrict__ x,
                      const float* __restrict__ lin_w, const float* __restrict__ lin_b,
                      const float* __restrict__ att_w, const float* __restrict__ att_b) {
    __shared__ float red[256];
    int b = blockIdx.x;
    int tid = threadIdx.x;
    if (b < NN) {
        float p = x[b * DD + tid] * att_w[DD + tid];
        float s = blk_reduce(p, red);
        if (tid == 0) g_sscore[b] = s;
    } else if (b < NN + DD) {
        int r = b - NN;
        float p = lin_w[r * DD + tid] * att_w[tid];
        float s = blk_reduce(p, red);
        if (tid == 0) g_v[r] = s;
    } else {
        float p = lin_b[tid] * att_w[tid];
        float s = blk_reduce(p, red);
        if (tid == 0) g_cconst = s + att_b[0];
    }
}

// one block per dst node: x_q (max), score, softmax, xn, and LEConv dots
__global__ void k_node(const float* __restrict__ x,
                       const float* __restrict__ le1_w, const float* __restrict__ le1_b,
                       const float* __restrict__ le2_w,
                       const float* __restrict__ le3_w, const float* __restrict__ le3_b) {
    __shared__ int   ssrc[512];
    __shared__ float ssc[512];
    __shared__ float red[256];
    __shared__ float sh_q, sh_m, sh_sum;
    int i = blockIdx.x;
    int tid = threadIdx.x;
    int eb = g_rp_dst[i];
    int deg = g_rp_dst[i + 1] - eb;

    for (int e = tid; e < deg; e += 256) ssrc[e] = g_esrc[eb + e];
    __syncthreads();

    // x_q[tid] = max over neighbors
    float xq = -INFINITY;
#pragma unroll 4
    for (int e = 0; e < deg; e++) xq = fmaxf(xq, x[ssrc[e] * DD + tid]);

    float qdot = blk_reduce(xq * g_v[tid], red);
    if (tid == 0) sh_q = qdot + g_cconst;
    __syncthreads();

    for (int e = tid; e < deg; e += 256) {
        float sc = sh_q + g_sscore[ssrc[e]];
        ssc[e] = (sc >= 0.0f) ? sc : NEG_SLOPE * sc;
    }
    __syncthreads();
    if (tid < 32) {
        float m = -INFINITY;
        for (int e = tid; e < deg; e += 32) m = fmaxf(m, ssc[e]);
#pragma unroll
        for (int off = 16; off > 0; off >>= 1)
            m = fmaxf(m, __shfl_xor_sync(0xffffffffu, m, off));
        if (tid == 0) sh_m = m;
    }
    __syncthreads();
    for (int e = tid; e < deg; e += 256) ssc[e] = expf(ssc[e] - sh_m);
    __syncthreads();
    if (tid < 32) {
        float s = 0.0f;
        for (int e = tid; e < deg; e += 32) s += ssc[e];
#pragma unroll
        for (int off = 16; off > 0; off >>= 1)
            s += __shfl_xor_sync(0xffffffffu, s, off);
        if (tid == 0) sh_sum = s;
    }
    __syncthreads();
    for (int e = tid; e < deg; e += 256) {
        float s = ssc[e] / sh_sum;
        ssc[e] = s;
        g_epack[eb + e] = make_float2(__int_as_float(ssrc[e]), s);
    }
    __syncthreads();

    // xn[i, tid] = sum_e score_e * x[src_e, tid]
    float acc = 0.0f;
#pragma unroll 4
    for (int e = 0; e < deg; e++) acc += ssc[e] * x[ssrc[e] * DD + tid];
    g_xn[i * DD + tid] = acc;

    float d1 = blk_reduce(acc * le1_w[tid], red);
    float d2 = blk_reduce(acc * le2_w[tid], red);
    float d3 = blk_reduce(acc * le3_w[tid], red);
    if (tid == 0) {
        g_a[i] = d1 + le1_b[0];
        g_basev[i] = d3 + le3_b[0] - (float)deg * d2;
    }
}

__global__ void k_fitness() {
    __shared__ float red[256];
    int i = blockIdx.x;
    int tid = threadIdx.x;
    int eb = g_rp_dst[i];
    int deg = g_rp_dst[i + 1] - eb;
    float agg = 0.0f;
    for (int e = tid; e < deg; e += 256) agg += g_a[g_esrc[eb + e]];
    float s = blk_reduce(agg, red);
    if (tid == 0) {
        float z = g_basev[i] + s;
        g_fit[i] = 1.0f / (1.0f + expf(-z));
    }
}

// exact stable top-k via rank counting
__global__ void k_rank(float* __restrict__ out, long long out_size) {
    __shared__ int redi[256];
    int i = blockIdx.x;
    int tid = threadIdx.x;
    float fi = g_fit[i];
    int cnt = 0;
    for (int j = tid; j < NN; j += 256) {
        float fj = g_fit[j];
        cnt += (fj > fi) || (fj == fi && j < i);
    }
    redi[tid] = cnt;
    __syncthreads();
    for (int off = 128; off > 0; off >>= 1) {
        if (tid < off) redi[tid] += redi[tid + off];
        __syncthreads();
    }
    if (tid == 0) {
        int rank = redi[0];
        if (rank < KK) {
            g_perm[rank] = i;
            long long idx = (long long)PERM_OFF + rank;
            if (idx < out_size) out[idx] = (float)i;
        }
    }
}

// PTILE output rows per block: U[src*PTILE + r] in dynamic smem (64 KB),
// warp-parallel build, float4-vectorized thread-per-q contraction.
// Also writes this block's PTILE x_out rows (folded former k_xout).
__global__ void k_ac(float* __restrict__ out, long long out_size) {
    extern __shared__ float U[];             // PTILE * NN floats
    __shared__ int s_eb[PTILE], s_deg[PTILE], s_pp[PTILE];
    int tid = threadIdx.x;
    int p0 = blockIdx.x * PTILE;

    float4* U4 = (float4*)U;
    for (int m = tid; m < PTILE * NN / 4; m += ACT)
        U4[m] = make_float4(0.f, 0.f, 0.f, 0.f);
    if (tid < PTILE) {
        int pp = g_perm[p0 + tid];
        int b = g_rp_dst[pp];
        s_pp[tid] = pp;
        s_eb[tid] = b;
        s_deg[tid] = g_rp_dst[pp + 1] - b;
    }
    __syncthreads();

    // ---- x_out rows for this tile (folded k_xout) ----
    for (int m = tid; m < PTILE * DD; m += ACT) {
        int r = m >> 8;                      // DD == 256
        int c = m & (DD - 1);
        int pp = s_pp[r];
        long long idx = (long long)XOUT_OFF + (long long)(p0 + r) * DD + c;
        if (idx < out_size) out[idx] = g_xn[pp * DD + c] * g_fit[pp];
    }

    // ---- build phase: warp w handles row (w & 3), e1 strided by 2 ----
    {
        int warp = tid >> 5, lane = tid & 31;
        int r = warp & (PTILE - 1);
        int estart = warp >> 2;              // 0 or 1
        int eb = s_eb[r], deg = s_deg[r];
        for (int e1 = estart; e1 < deg; e1 += 2) {
            float2 pk = g_epack[eb + e1];    // broadcast across warp
            int   i = __float_as_int(pk.x);
            float s = pk.y;
            int ob = g_rp_src[i];
            int od = g_rp_src[i + 1] - ob;
            for (int o = lane; o < od; o += 32)
                atomicAdd(&U[g_edst[ob + o] * PTILE + r], s * g_ew[ob + o]);
        }
    }
    __syncthreads();

    // ---- contraction: thread-per-q, PTILE accumulators ----
    for (int q = tid; q < KK; q += ACT) {
        int pq = g_perm[q];
        int qb = g_rp_dst[pq];
        int qd = g_rp_dst[pq + 1] - qb;
        float acc[PTILE];
#pragma unroll
        for (int r = 0; r < PTILE; r++) acc[r] = 0.f;
#pragma unroll 4
        for (int e = 0; e < qd; e++) {
            float2 pk = g_epack[qb + e];
            int   src = __float_as_int(pk.x);
            float sc  = pk.y;
            float4 a = U4[src];
            acc[0] += sc * a.x; acc[1] += sc * a.y;
            acc[2] += sc * a.z; acc[3] += sc * a.w;
        }
#pragma unroll
        for (int r = 0; r < PTILE; r++) {
            int p = p0 + r;
            float v = (q == p) ? 0.f : acc[r];
            long long idx = (long long)AC_OFF + (long long)p * KK + q;
            if (idx < out_size) out[idx] = v;
        }
    }
}

// ---------------- launch ----------------
extern "C" void kernel_launch(void* const* d_in, const int* in_sizes, int n_in,
                              void* d_out, int out_size) {
    const float* x      = (const float*)d_in[0];
    const int*   ei     = (const int*)  d_in[1];
    const float* ew     = (const float*)d_in[2];
    const float* lin_w  = (const float*)d_in[3];
    const float* lin_b  = (const float*)d_in[4];
    const float* att_w  = (const float*)d_in[5];
    const float* att_b  = (const float*)d_in[6];
    const float* le1_w  = (const float*)d_in[7];
    const float* le1_b  = (const float*)d_in[8];
    const float* le2_w  = (const float*)d_in[9];
    const float* le3_w  = (const float*)d_in[10];
    const float* le3_b  = (const float*)d_in[11];
    float* out = (float*)d_out;
    long long osz = (long long)out_size;

    static int smem_set = 0;
    if (!smem_set) {
        cudaFuncSetAttribute(k_ac, cudaFuncAttributeMaxDynamicSharedMemorySize,
                             PTILE * NN * (int)sizeof(float));
        smem_set = 1;
    }

    k_zero<<<NN / 256, 256>>>();
    k_count<<<E0N / 256, 256>>>(ei);
    k_scan2<<<2, 1024>>>();
    k_fill<<<(E0N + NN) / 256, 256>>>(ei, ew);

    k_pre<<<NN + DD + 1, 256>>>(x, lin_w, lin_b, att_w, att_b);

    k_node<<<NN, 256>>>(x, le1_w, le1_b, le2_w, le3_w, le3_b);
    k_fitness<<<NN, 256>>>();
    k_rank<<<NN, 256>>>(out, osz);
    k_ac<<<KK / PTILE, ACT, PTILE * NN * (int)sizeof(float)>>>(out, osz);
}

// round 9
// speedup vs baseline: 1.4680x; 1.4680x over previous
#include <cuda_runtime.h>
#include <math.h>

#define NN     4096
#define DD     256
#define E0N    131072
#define EN     (E0N + NN)      // 135168 (with self loops)
#define KK     2048
#define NEG_SLOPE 0.2f

#define XOUT_OFF 0
#define AC_OFF   (KK * DD)                 // 524288
#define PERM_OFF (AC_OFF + KK * KK)        // 4718592

#define PTILE  14
#define ACT    512   // threads in k_ac
#define NWARP  (ACT / 32)

// ---------------- device scratch (static, no allocation) ----------------
__device__ int    g_cnt_dst[NN];
__device__ int    g_cnt_src[NN];
__device__ int    g_rp_dst[NN + 1];
__device__ int    g_rp_src[NN + 1];
__device__ int    g_off_dst[NN];
__device__ int    g_off_src[NN];
__device__ int    g_esrc[EN];     // dst-CSR: src node of each in-edge
__device__ float2 g_epack[EN];    // dst-CSR: (src as int bits, normalized score)
__device__ int    g_edst[EN];     // src-CSR: dst node of each out-edge
__device__ float  g_ew[EN];       // src-CSR: edge weight
__device__ float  g_v[DD];        // lin_w @ att_top
__device__ float  g_cconst;       // lin_b . att_top + att_b
__device__ float  g_sscore[NN];   // x[j] . att_bot
__device__ float  g_xn[NN * DD];
__device__ float  g_a[NN];
__device__ float  g_basev[NN];
__device__ float  g_fit[NN];
__device__ int    g_perm[KK];

// ---------------- kernels ----------------
__global__ void k_zero() {
    int i = blockIdx.x * blockDim.x + threadIdx.x;
    if (i < NN) { g_cnt_dst[i] = 0; g_cnt_src[i] = 0; }
}

__global__ void k_count(const int* __restrict__ ei) {
    int e = blockIdx.x * blockDim.x + threadIdx.x;
    if (e < E0N) {
        atomicAdd(&g_cnt_dst[ei[E0N + e]], 1);
        atomicAdd(&g_cnt_src[ei[e]], 1);
    }
}

// grid=2: block 0 scans dst counts, block 1 scans src counts.
// Adds the implicit +1 self loop per node and writes both rp and off.
__global__ void k_scan2() {
    __shared__ int sp[1024];
    const int* cnt = (blockIdx.x == 0) ? g_cnt_dst : g_cnt_src;
    int* rp  = (blockIdx.x == 0) ? g_rp_dst  : g_rp_src;
    int* off = (blockIdx.x == 0) ? g_off_dst : g_off_src;
    int tid = threadIdx.x;
    int base = tid * 4;
    int loc[4];
    int s = 0;
#pragma unroll
    for (int j = 0; j < 4; j++) { loc[j] = cnt[base + j] + 1; s += loc[j]; }
    sp[tid] = s;
    __syncthreads();
    for (int o = 1; o < 1024; o <<= 1) {
        int v = 0;
        if (tid >= o) v = sp[tid - o];
        __syncthreads();
        if (tid >= o) sp[tid] += v;
        __syncthreads();
    }
    int run = (tid > 0) ? sp[tid - 1] : 0;
#pragma unroll
    for (int j = 0; j < 4; j++) { rp[base + j] = run; off[base + j] = run; run += loc[j]; }
    if (tid == 1023) rp[NN] = run;
}

__global__ void k_fill(const int* __restrict__ ei, const float* __restrict__ ew) {
    int t = blockIdx.x * blockDim.x + threadIdx.x;
    if (t >= E0N + NN) return;
    int s, d; float w;
    if (t < E0N) { s = ei[t]; d = ei[E0N + t]; w = ew[t]; }
    else         { s = t - E0N; d = s; w = 1.0f; }
    int slot = atomicAdd(&g_off_dst[d], 1);
    g_esrc[slot] = s;
    int slot2 = atomicAdd(&g_off_src[s], 1);
    g_edst[slot2] = d;
    g_ew[slot2] = w;
}

__device__ __forceinline__ float blk_reduce(float val, float* red) {
    int tid = threadIdx.x;
    red[tid] = val;
    __syncthreads();
    for (int off = 128; off > 0; off >>= 1) {
        if (tid < off) red[tid] += red[tid + off];
        __syncthreads();
    }
    float r = red[0];
    __syncthreads();
    return r;
}

// fused small precomputations: sscore (NN blocks) | v (DD blocks) | c (1 block)
__global__ void k_pre(const float* __restrict__ x,
                      const float* __restrict__ lin_w, const float* __restrict__ lin_b,
                      const float* __restrict__ att_w, const float* __restrict__ att_b) {
    __shared__ float red[256];
    int b = blockIdx.x;
    int tid = threadIdx.x;
    if (b < NN) {
        float p = x[b * DD + tid] * att_w[DD + tid];
        float s = blk_reduce(p, red);
        if (tid == 0) g_sscore[b] = s;
    } else if (b < NN + DD) {
        int r = b - NN;
        float p = lin_w[r * DD + tid] * att_w[tid];
        float s = blk_reduce(p, red);
        if (tid == 0) g_v[r] = s;
    } else {
        float p = lin_b[tid] * att_w[tid];
        float s = blk_reduce(p, red);
        if (tid == 0) g_cconst = s + att_b[0];
    }
}

// one block per dst node: x_q (max), score, softmax, xn, and LEConv dots
__global__ void k_node(const float* __restrict__ x,
                       const float* __restrict__ le1_w, const float* __restrict__ le1_b,
                       const float* __restrict__ le2_w,
                       const float* __restrict__ le3_w, const float* __restrict__ le3_b) {
    __shared__ int   ssrc[512];
    __shared__ float ssc[512];
    __shared__ float red[256];
    __shared__ float sh_q, sh_m, sh_sum;
    int i = blockIdx.x;
    int tid = threadIdx.x;
    int eb = g_rp_dst[i];
    int deg = g_rp_dst[i + 1] - eb;

    for (int e = tid; e < deg; e += 256) ssrc[e] = g_esrc[eb + e];
    __syncthreads();

    // x_q[tid] = max over neighbors
    float xq = -INFINITY;
#pragma unroll 4
    for (int e = 0; e < deg; e++) xq = fmaxf(xq, x[ssrc[e] * DD + tid]);

    float qdot = blk_reduce(xq * g_v[tid], red);
    if (tid == 0) sh_q = qdot + g_cconst;
    __syncthreads();

    for (int e = tid; e < deg; e += 256) {
        float sc = sh_q + g_sscore[ssrc[e]];
        ssc[e] = (sc >= 0.0f) ? sc : NEG_SLOPE * sc;
    }
    __syncthreads();
    if (tid < 32) {
        float m = -INFINITY;
        for (int e = tid; e < deg; e += 32) m = fmaxf(m, ssc[e]);
#pragma unroll
        for (int off = 16; off > 0; off >>= 1)
            m = fmaxf(m, __shfl_xor_sync(0xffffffffu, m, off));
        if (tid == 0) sh_m = m;
    }
    __syncthreads();
    for (int e = tid; e < deg; e += 256) ssc[e] = expf(ssc[e] - sh_m);
    __syncthreads();
    if (tid < 32) {
        float s = 0.0f;
        for (int e = tid; e < deg; e += 32) s += ssc[e];
#pragma unroll
        for (int off = 16; off > 0; off >>= 1)
            s += __shfl_xor_sync(0xffffffffu, s, off);
        if (tid == 0) sh_sum = s;
    }
    __syncthreads();
    for (int e = tid; e < deg; e += 256) {
        float s = ssc[e] / sh_sum;
        ssc[e] = s;
        g_epack[eb + e] = make_float2(__int_as_float(ssrc[e]), s);
    }
    __syncthreads();

    // xn[i, tid] = sum_e score_e * x[src_e, tid]
    float acc = 0.0f;
#pragma unroll 4
    for (int e = 0; e < deg; e++) acc += ssc[e] * x[ssrc[e] * DD + tid];
    g_xn[i * DD + tid] = acc;

    float d1 = blk_reduce(acc * le1_w[tid], red);
    float d2 = blk_reduce(acc * le2_w[tid], red);
    float d3 = blk_reduce(acc * le3_w[tid], red);
    if (tid == 0) {
        g_a[i] = d1 + le1_b[0];
        g_basev[i] = d3 + le3_b[0] - (float)deg * d2;
    }
}

__global__ void k_fitness() {
    __shared__ float red[256];
    int i = blockIdx.x;
    int tid = threadIdx.x;
    int eb = g_rp_dst[i];
    int deg = g_rp_dst[i + 1] - eb;
    float agg = 0.0f;
    for (int e = tid; e < deg; e += 256) agg += g_a[g_esrc[eb + e]];
    float s = blk_reduce(agg, red);
    if (tid == 0) {
        float z = g_basev[i] + s;
        g_fit[i] = 1.0f / (1.0f + expf(-z));
    }
}

// exact stable top-k via rank counting
__global__ void k_rank(float* __restrict__ out, long long out_size) {
    __shared__ int redi[256];
    int i = blockIdx.x;
    int tid = threadIdx.x;
    float fi = g_fit[i];
    int cnt = 0;
    for (int j = tid; j < NN; j += 256) {
        float fj = g_fit[j];
        cnt += (fj > fi) || (fj == fi && j < i);
    }
    redi[tid] = cnt;
    __syncthreads();
    for (int off = 128; off > 0; off >>= 1) {
        if (tid < off) redi[tid] += redi[tid + off];
        __syncthreads();
    }
    if (tid == 0) {
        int rank = redi[0];
        if (rank < KK) {
            g_perm[rank] = i;
            long long idx = (long long)PERM_OFF + rank;
            if (idx < out_size) out[idx] = (float)i;
        }
    }
}

// PTILE output rows per block: U[src*PTILE + r] in dynamic smem (224 KB),
// warp-parallel build over flattened (row, e1) pairs, thread-per-q contraction.
// Grid = ceil(KK/PTILE) = 147 blocks -> exactly one wave on 148 SMs.
// Also writes this block's PTILE x_out rows (folded former k_xout).
__global__ void k_ac(float* __restrict__ out, long long out_size) {
    extern __shared__ float U[];             // PTILE * NN floats
    __shared__ int s_eb[PTILE], s_deg[PTILE], s_pp[PTILE];
    __shared__ int s_maxdeg;
    int tid = threadIdx.x;
    int p0 = blockIdx.x * PTILE;

    float4* U4z = (float4*)U;
    for (int m = tid; m < PTILE * NN / 4; m += ACT)
        U4z[m] = make_float4(0.f, 0.f, 0.f, 0.f);
    if (tid < PTILE) {
        int p = p0 + tid;
        int pp = (p < KK) ? g_perm[p] : 0;
        int b  = (p < KK) ? g_rp_dst[pp] : 0;
        int dg = (p < KK) ? (g_rp_dst[pp + 1] - b) : 0;
        s_pp[tid] = pp;
        s_eb[tid] = b;
        s_deg[tid] = dg;
    }
    __syncthreads();
    if (tid == 0) {
        int m = 0;
#pragma unroll
        for (int r = 0; r < PTILE; r++) m = (s_deg[r] > m) ? s_deg[r] : m;
        s_maxdeg = m;
    }

    // ---- x_out rows for this tile (folded k_xout) ----
    for (int m = tid; m < PTILE * DD; m += ACT) {
        int r = m >> 8;                      // DD == 256
        int c = m & (DD - 1);
        int p = p0 + r;
        if (p < KK) {
            int pp = s_pp[r];
            long long idx = (long long)XOUT_OFF + (long long)p * DD + c;
            if (idx < out_size) out[idx] = g_xn[pp * DD + c] * g_fit[pp];
        }
    }
    __syncthreads();

    // ---- build phase: warps over flattened (r, e1) pairs ----
    {
        int warp = tid >> 5, lane = tid & 31;
        int lim = PTILE * s_maxdeg;
        for (int t = warp; t < lim; t += NWARP) {
            int r  = t % PTILE;
            int e1 = t / PTILE;
            if (e1 >= s_deg[r]) continue;
            float2 pk = g_epack[s_eb[r] + e1]; // broadcast across warp
            int   i = __float_as_int(pk.x);
            float s = pk.y;
            int ob = g_rp_src[i];
            int od = g_rp_src[i + 1] - ob;
            for (int o = lane; o < od; o += 32)
                atomicAdd(&U[g_edst[ob + o] * PTILE + r], s * g_ew[ob + o]);
        }
    }
    __syncthreads();

    // ---- contraction: thread-per-q, PTILE accumulators ----
    for (int q = tid; q < KK; q += ACT) {
        int pq = g_perm[q];
        int qb = g_rp_dst[pq];
        int qd = g_rp_dst[pq + 1] - qb;
        float acc[PTILE];
#pragma unroll
        for (int r = 0; r < PTILE; r++) acc[r] = 0.f;
#pragma unroll 4
        for (int e = 0; e < qd; e++) {
            float2 pk = g_epack[qb + e];
            int   src = __float_as_int(pk.x);
            float sc  = pk.y;
            const float2* u2 = (const float2*)&U[src * PTILE]; // 56B row, 8B aligned
#pragma unroll
            for (int j = 0; j < PTILE / 2; j++) {
                float2 u = u2[j];
                acc[2 * j]     += sc * u.x;
                acc[2 * j + 1] += sc * u.y;
            }
        }
#pragma unroll
        for (int r = 0; r < PTILE; r++) {
            int p = p0 + r;
            if (p < KK) {
                float v = (q == p) ? 0.f : acc[r];
                long long idx = (long long)AC_OFF + (long long)p * KK + q;
                if (idx < out_size) out[idx] = v;
            }
        }
    }
}

// ---------------- launch ----------------
extern "C" void kernel_launch(void* const* d_in, const int* in_sizes, int n_in,
                              void* d_out, int out_size) {
    const float* x      = (const float*)d_in[0];
    const int*   ei     = (const int*)  d_in[1];
    const float* ew     = (const float*)d_in[2];
    const float* lin_w  = (const float*)d_in[3];
    const float* lin_b  = (const float*)d_in[4];
    const float* att_w  = (const float*)d_in[5];
    const float* att_b  = (const float*)d_in[6];
    const float* le1_w  = (const float*)d_in[7];
    const float* le1_b  = (const float*)d_in[8];
    const float* le2_w  = (const float*)d_in[9];
    const float* le3_w  = (const float*)d_in[10];
    const float* le3_b  = (const float*)d_in[11];
    float* out = (float*)d_out;
    long long osz = (long long)out_size;

    static int smem_set = 0;
    if (!smem_set) {
        cudaFuncSetAttribute(k_ac, cudaFuncAttributeMaxDynamicSharedMemorySize,
                             PTILE * NN * (int)sizeof(float));
        smem_set = 1;
    }

    k_zero<<<NN / 256, 256>>>();
    k_count<<<E0N / 256, 256>>>(ei);
    k_scan2<<<2, 1024>>>();
    k_fill<<<(E0N + NN) / 256, 256>>>(ei, ew);

    k_pre<<<NN + DD + 1, 256>>>(x, lin_w, lin_b, att_w, att_b);

    k_node<<<NN, 256>>>(x, le1_w, le1_b, le2_w, le3_w, le3_b);
    k_fitness<<<NN, 256>>>();
    k_rank<<<NN, 256>>>(out, osz);
    k_ac<<<(KK + PTILE - 1) / PTILE, ACT, PTILE * NN * (int)sizeof(float)>>>(out, osz);
}